// round 7
// baseline (speedup 1.0000x reference)
#include <cuda_runtime.h>
#include <cuda_bf16.h>
#include <cstdint>

#define BB 8
#define NN 10000
#define EE 160000
#define FF 64
#define BN (BB * NN)          // 80000 nodes
#define BE (BB * EE)          // 1280000 edges
#define SCAN_BLKS ((BN + 1023) / 1024)   // 79

// ---- scratch (device globals; no allocation allowed) ----
__device__ int   g_is64;
__device__ int   g_degi[BN];
__device__ float g_dinv[BN];
__device__ int   g_rowstart[BN];
__device__ int   g_cursor[BN];
__device__ int   g_scantmp[BN];
__device__ int   g_partial[SCAN_BLKS];
__device__ int2  g_rc[BE];        // packed (row, col)
__device__ int2  g_csr[BE];       // {col, norm-bits} grouped by row
__device__ float g_pA[BN * FF];   // ping
__device__ float g_pB[BN * FF];   // pong

// ---------------------------------------------------------------------------
__device__ __forceinline__ void fma2(unsigned long long& acc,
                                     unsigned long long a,
                                     unsigned long long b) {
    asm("fma.rn.f32x2 %0, %1, %2, %0;" : "+l"(acc) : "l"(a), "l"(b));
}
__device__ __forceinline__ unsigned long long pack2(float lo, float hi) {
    unsigned long long r;
    asm("mov.b64 %0, {%1, %2};" : "=l"(r) : "f"(lo), "f"(hi));
    return r;
}
__device__ __forceinline__ void unpack2(unsigned long long v, float& lo, float& hi) {
    asm("mov.b64 {%0, %1}, %2;" : "=f"(lo), "=f"(hi) : "l"(v));
}

// ---------------------------------------------------------------------------
// zero degrees; thread 0 also detects edge_index width
__global__ void setup_k(const void* ei, int* __restrict__ degp) {
    int i = blockIdx.x * blockDim.x + threadIdx.x;
    for (; i < BN; i += gridDim.x * blockDim.x) degp[i] = 0;
    if (threadIdx.x == 0 && blockIdx.x == 0) {
        const long long* p = (const long long*)ei;
        int ok = 1;
        for (int k = 0; k < 64; k++) {
            long long v = p[k];
            if (v < 0 || v >= NN) { ok = 0; break; }
        }
        g_is64 = ok;
    }
}

// edge pairs -> int32 with per-graph offset (packed int2); degree histogram
__global__ void edges_k(const void* __restrict__ ei) {
    int e = blockIdx.x * blockDim.x + threadIdx.x;
    if (e >= BE) return;
    int r, c;
    if (g_is64) {
        const long long* p = (const long long*)ei;
        r = (int)p[2 * e];
        c = (int)p[2 * e + 1];
    } else {
        const int* p = (const int*)ei;
        r = p[2 * e];
        c = p[2 * e + 1];
    }
    r = min(max(r, 0), NN - 1);
    c = min(max(c, 0), NN - 1);
    int b = e / EE;
    r += b * NN;
    c += b * NN;
    g_rc[e] = make_int2(r, c);
    atomicAdd(&g_degi[r], 1);
}

// ---- two-level exclusive scan of degrees ----
__global__ void __launch_bounds__(1024, 1) scanA_k() {
    __shared__ int warpsum[32];
    int tid = threadIdx.x, lane = tid & 31, wid = tid >> 5;
    int i = blockIdx.x * 1024 + tid;
    int v = (i < BN) ? g_degi[i] : 0;
    int x = v;
#pragma unroll
    for (int off = 1; off < 32; off <<= 1) {
        int y = __shfl_up_sync(0xffffffffu, x, off);
        if (lane >= off) x += y;
    }
    if (lane == 31) warpsum[wid] = x;
    __syncthreads();
    if (wid == 0) {
        int s = warpsum[lane];
        int xs = s;
#pragma unroll
        for (int off = 1; off < 32; off <<= 1) {
            int y = __shfl_up_sync(0xffffffffu, xs, off);
            if (lane >= off) xs += y;
        }
        warpsum[lane] = xs - s;
    }
    __syncthreads();
    int excl = warpsum[wid] + x - v;
    if (i < BN) g_scantmp[i] = excl;
    if (tid == 1023) g_partial[blockIdx.x] = excl + v;
}

__global__ void scanB_k() {
    int lane = threadIdx.x;
    int carry = 0;
    for (int base = 0; base < SCAN_BLKS; base += 32) {
        int idx = base + lane;
        int v = (idx < SCAN_BLKS) ? g_partial[idx] : 0;
        int x = v;
#pragma unroll
        for (int off = 1; off < 32; off <<= 1) {
            int y = __shfl_up_sync(0xffffffffu, x, off);
            if (lane >= off) x += y;
        }
        if (idx < SCAN_BLKS) g_partial[idx] = carry + x - v;
        carry += __shfl_sync(0xffffffffu, x, 31);
    }
}

__global__ void scanC_k() {   // add offsets; fused dinv
    int i = blockIdx.x * blockDim.x + threadIdx.x;
    if (i >= BN) return;
    int start = g_scantmp[i] + g_partial[i >> 10];
    g_rowstart[i] = start;
    g_cursor[i]   = start;
    int d = g_degi[i];
    g_dinv[i] = d > 0 ? rsqrtf((float)d) : 0.f;
}

// scatter edges into CSR slots
__global__ void fill_k() {
    int e = blockIdx.x * blockDim.x + threadIdx.x;
    if (e >= BE) return;
    int2 rc = g_rc[e];
    int pos = atomicAdd(&g_cursor[rc.x], 1);
    float nm = g_dinv[rc.x] * g_dinv[rc.y];
    g_csr[pos] = make_int2(rc.y, __float_as_int(nm));
}

// ---------------------------------------------------------------------------
// Fused GCN layer:  out = relu?( (A·h)·W^T + s·b )  where s[row] = Σ_e norm.
// Block = 256 threads = 8 warps handles 32 nodes.
//  Phase 1: warp aggregates 4 nodes; lane owns features (2l, 2l+1) as f32x2.
//           meta via warp-uniform __ldg (HW broadcast); s accumulated free.
//           Result written to smem replicated as (v,v) pairs for phase 2.
//  Phase 2: R=4 row blocking; per k: 1 LDS.64 weight-pair + 4 broadcast
//           LDS.64 x-pairs + 4 FFMA2  -> ~90% FMA-pipe efficiency.
template <bool RELU>
__global__ void __launch_bounds__(256)
layer_k(const float* __restrict__ h, const float* __restrict__ W,
        const float* __restrict__ bias, float* __restrict__ out) {
    __shared__ float2 sWp[64 * 32];   // [k][l] = (W[l][k], W[l+32][k]) 16KB
    __shared__ float2 sagg[32 * 64];  // [r][k] = (v,v) replicated      16KB
    __shared__ float  sb[64];
    __shared__ float  ss[32];

    int tid = threadIdx.x;
    int w = tid >> 5, lane = tid & 31;
    int node0 = blockIdx.x * 32;

    // stage W & bias (needed only after the barrier)
    for (int idx = tid; idx < 2048; idx += 256) {
        int k = idx >> 5, l = idx & 31;
        sWp[idx] = make_float2(W[l * 64 + k], W[(l + 32) * 64 + k]);
    }
    if (tid < 64) sb[tid] = bias[tid];

    // ---- phase 1: aggregate 4 nodes per warp ----
    const unsigned long long* h64 = (const unsigned long long*)h;
#pragma unroll
    for (int j = 0; j < 4; j++) {
        int r = w * 4 + j;
        int node = node0 + r;
        int start = g_rowstart[node];
        int cnt   = g_degi[node];
        unsigned long long acc = 0;
        float s = 0.f;
#pragma unroll 2
        for (int e = 0; e < cnt; e++) {
            int2 meta = __ldg(&g_csr[start + e]);     // warp-uniform
            float nm = __int_as_float(meta.y);
            unsigned long long nm2;
            asm("mov.b64 %0, {%1, %1};" : "=l"(nm2) : "r"(meta.y));
            unsigned long long v = __ldg(h64 + (size_t)meta.x * 32 + lane);
            fma2(acc, nm2, v);
            s += nm;
        }
        float lo, hi;
        unpack2(acc, lo, hi);
        sagg[r * 64 + 2 * lane]     = make_float2(lo, lo);
        sagg[r * 64 + 2 * lane + 1] = make_float2(hi, hi);
        if (lane == 0) ss[r] = s;
    }
    __syncthreads();

    // ---- phase 2: 32x64 @ 64x64, R=4 rows per thread ----
    int r0 = w * 4;
    unsigned long long b2 = pack2(sb[lane], sb[lane + 32]);
    unsigned long long a0 = 0, a1 = 0, a2 = 0, a3 = 0;
    {
        float s0 = ss[r0], s1 = ss[r0+1], s2v = ss[r0+2], s3 = ss[r0+3];
        fma2(a0, b2, pack2(s0, s0));
        fma2(a1, b2, pack2(s1, s1));
        fma2(a2, b2, pack2(s2v, s2v));
        fma2(a3, b2, pack2(s3, s3));
    }
    const unsigned long long* wp = (const unsigned long long*)sWp;
    const unsigned long long* xp = (const unsigned long long*)sagg;
#pragma unroll
    for (int k = 0; k < 64; k++) {
        unsigned long long wk = wp[k * 32 + lane];
        fma2(a0, wk, xp[(r0 + 0) * 64 + k]);
        fma2(a1, wk, xp[(r0 + 1) * 64 + k]);
        fma2(a2, wk, xp[(r0 + 2) * 64 + k]);
        fma2(a3, wk, xp[(r0 + 3) * 64 + k]);
    }
    float lo, hi;
#define STORE_ROW(AJ, J)                                                     \
    unpack2(AJ, lo, hi);                                                     \
    if (RELU) { lo = fmaxf(lo, 0.f); hi = fmaxf(hi, 0.f); }                  \
    out[(size_t)(node0 + r0 + J) * 64 + lane]      = lo;                     \
    out[(size_t)(node0 + r0 + J) * 64 + lane + 32] = hi;
    STORE_ROW(a0, 0) STORE_ROW(a1, 1) STORE_ROW(a2, 2) STORE_ROW(a3, 3)
#undef STORE_ROW
}

// ---------------------------------------------------------------------------
extern "C" void kernel_launch(void* const* d_in, const int* in_sizes, int n_in,
                              void* d_out, int out_size) {
    const float* x = nullptr;
    const void*  ei = nullptr;
    const float* Ws[3] = {nullptr, nullptr, nullptr};
    const float* bs[3] = {nullptr, nullptr, nullptr};
    int nW = 0, nb = 0;
    for (int i = 0; i < n_in; i++) {
        long long sz = in_sizes[i];
        if (sz == (long long)BN * FF)      x  = (const float*)d_in[i];
        else if (sz == (long long)BE * 2)  ei = d_in[i];
        else if (sz == FF * FF) { if (nW < 3) Ws[nW++] = (const float*)d_in[i]; }
        else if (sz == FF)      { if (nb < 3) bs[nb++] = (const float*)d_in[i]; }
    }
    float* out = (float*)d_out;

    int   *degi;
    float *pA, *pB;
    cudaGetSymbolAddress((void**)&degi, g_degi);
    cudaGetSymbolAddress((void**)&pA,   g_pA);
    cudaGetSymbolAddress((void**)&pB,   g_pB);

    const int TPB = 256;
    const int edgeBlocks  = (BE + TPB - 1) / TPB;     // 5000
    const int nodeBlocks  = (BN + TPB - 1) / TPB;     // 313
    const int layerBlocks = BN / 32;                  // 2500

    // CSR build
    setup_k<<<nodeBlocks, TPB>>>(ei, degi);
    edges_k<<<edgeBlocks, TPB>>>(ei);
    scanA_k<<<SCAN_BLKS, 1024>>>();
    scanB_k<<<1, 32>>>();
    scanC_k<<<nodeBlocks, TPB>>>();
    fill_k<<<edgeBlocks, TPB>>>();

    // fused layers: out_l = relu?((A·h)W^T + s·b)
    layer_k<true ><<<layerBlocks, TPB>>>(x,  Ws[0], bs[0], pA);
    layer_k<true ><<<layerBlocks, TPB>>>(pA, Ws[1], bs[1], pB);
    layer_k<false><<<layerBlocks, TPB>>>(pB, Ws[2], bs[2], out);
}

// round 8
// speedup vs baseline: 1.0829x; 1.0829x over previous
#include <cuda_runtime.h>
#include <cuda_bf16.h>
#include <cstdint>

#define BB 8
#define NN 10000
#define EE 160000
#define FF 64
#define BN (BB * NN)          // 80000 nodes
#define BE (BB * EE)          // 1280000 edges
#define SCAN_BLKS ((BN + 1023) / 1024)   // 79

#define FLAG_AGG    (1ULL << 62)
#define FLAG_PREFIX (2ULL << 62)
#define VAL_MASK    ((1ULL << 62) - 1)

// ---- scratch (device globals; no allocation allowed) ----
__device__ int   g_is64;
__device__ int   g_degi[BN];
__device__ float g_dinv[BN];
__device__ int   g_rowstart[BN];
__device__ int   g_cursor[BN];
__device__ unsigned long long g_state[SCAN_BLKS];  // lookback state
__device__ int2  g_rc[BE];        // packed (row, col)
__device__ int2  g_csr[BE];       // {col, norm-bits} grouped by row
__device__ float g_t[BN * FF];    // post-linear features
__device__ float g_pA[BN * FF];   // ping
__device__ float g_pB[BN * FF];   // pong

// ---------------------------------------------------------------------------
__device__ __forceinline__ void fma2(unsigned long long& acc,
                                     unsigned long long a,
                                     unsigned long long b) {
    asm("fma.rn.f32x2 %0, %1, %2, %0;" : "+l"(acc) : "l"(a), "l"(b));
}
__device__ __forceinline__ unsigned long long pack2(float lo, float hi) {
    unsigned long long r;
    asm("mov.b64 %0, {%1, %2};" : "=l"(r) : "f"(lo), "f"(hi));
    return r;
}
__device__ __forceinline__ void unpack2(unsigned long long v, float& lo, float& hi) {
    asm("mov.b64 {%0, %1}, %2;" : "=f"(lo), "=f"(hi) : "l"(v));
}

// ---------------------------------------------------------------------------
// zero degi + lookback state; block 0 warp 0 does parallel dtype detection
__global__ void setup_k(const void* ei, int* __restrict__ degp) {
    int i = blockIdx.x * blockDim.x + threadIdx.x;
    for (; i < BN; i += gridDim.x * blockDim.x) degp[i] = 0;
    if (blockIdx.x == 0 && threadIdx.x < 32) {
        if (threadIdx.x < SCAN_BLKS) {
            g_state[threadIdx.x] = 0;
            if (threadIdx.x + 32 < SCAN_BLKS) g_state[threadIdx.x + 32] = 0;
            if (threadIdx.x + 64 < SCAN_BLKS) g_state[threadIdx.x + 64] = 0;
        }
        const long long* p = (const long long*)ei;
        long long v0 = p[threadIdx.x];
        long long v1 = p[threadIdx.x + 32];
        bool bad = (v0 < 0) | (v0 >= NN) | (v1 < 0) | (v1 >= NN);
        unsigned m = __ballot_sync(0xffffffffu, bad);
        if (threadIdx.x == 0) g_is64 = (m == 0) ? 1 : 0;
    }
}

// edge pairs -> int32 with per-graph offset (packed int2); degree histogram
__global__ void edges_k(const void* __restrict__ ei) {
    int e = blockIdx.x * blockDim.x + threadIdx.x;
    if (e >= BE) return;
    int r, c;
    if (g_is64) {
        const long long* p = (const long long*)ei;
        r = (int)p[2 * e];
        c = (int)p[2 * e + 1];
    } else {
        const int* p = (const int*)ei;
        r = p[2 * e];
        c = p[2 * e + 1];
    }
    r = min(max(r, 0), NN - 1);
    c = min(max(c, 0), NN - 1);
    int b = e / EE;
    r += b * NN;
    c += b * NN;
    g_rc[e] = make_int2(r, c);
    atomicAdd(&g_degi[r], 1);
}

// ---------------------------------------------------------------------------
// single-kernel scan: decoupled lookback (all 79 blocks co-resident).
// Produces rowstart/cursor (exclusive prefix) and dinv, in one launch.
__global__ void __launch_bounds__(1024, 1) scan_k() {
    __shared__ int warpsum[32];
    __shared__ int sTot;
    __shared__ unsigned long long sBase;
    int tid = threadIdx.x, lane = tid & 31, wid = tid >> 5;
    int b = blockIdx.x;
    int i = b * 1024 + tid;

    int v = (i < BN) ? g_degi[i] : 0;
    int x = v;
#pragma unroll
    for (int off = 1; off < 32; off <<= 1) {
        int y = __shfl_up_sync(0xffffffffu, x, off);
        if (lane >= off) x += y;
    }
    if (lane == 31) warpsum[wid] = x;
    __syncthreads();

    if (wid == 0) {
        int s = warpsum[lane];
        int xs = s;
#pragma unroll
        for (int off = 1; off < 32; off <<= 1) {
            int y = __shfl_up_sync(0xffffffffu, xs, off);
            if (lane >= off) xs += y;
        }
        warpsum[lane] = xs - s;           // exclusive warp prefix
        if (lane == 31) sTot = xs;        // block total
        __syncwarp();
        int tot = sTot;

        if (b == 0) {
            if (lane == 0) {
                sBase = 0;
                atomicExch(&g_state[0], FLAG_PREFIX | (unsigned long long)tot);
            }
        } else {
            if (lane == 0)
                atomicExch(&g_state[b], FLAG_AGG | (unsigned long long)tot);
            // warp-parallel lookback
            unsigned long long run = 0;
            int j = b - 1;
            while (true) {
                int idx = j - lane;
                unsigned long long s64;
                if (idx >= 0) {
                    do {
                        s64 = *(volatile unsigned long long*)&g_state[idx];
                    } while ((s64 >> 62) == 0);
                } else {
                    s64 = FLAG_PREFIX;    // value 0
                }
                unsigned f = (unsigned)(s64 >> 62);
                unsigned long long val = s64 & VAL_MASK;
                unsigned pm = __ballot_sync(0xffffffffu, f == 2);
                if (pm) {
                    int lp = __ffs(pm) - 1;       // nearest prefix
                    unsigned long long c2 = (lane <= lp) ? val : 0;
#pragma unroll
                    for (int o = 16; o; o >>= 1)
                        c2 += __shfl_down_sync(0xffffffffu, c2, o);
                    run += __shfl_sync(0xffffffffu, c2, 0);
                    break;
                } else {
                    unsigned long long c2 = val;
#pragma unroll
                    for (int o = 16; o; o >>= 1)
                        c2 += __shfl_down_sync(0xffffffffu, c2, o);
                    run += __shfl_sync(0xffffffffu, c2, 0);
                    j -= 32;
                }
            }
            if (lane == 0) {
                sBase = run;
                atomicExch(&g_state[b],
                           FLAG_PREFIX | (run + (unsigned long long)tot));
            }
        }
    }
    __syncthreads();

    if (i < BN) {
        int start = (int)sBase + warpsum[wid] + (x - v);
        g_rowstart[i] = start;
        g_cursor[i]   = start;
        g_dinv[i] = v > 0 ? rsqrtf((float)v) : 0.f;
    }
}

// scatter edges into CSR slots
__global__ void fill_k() {
    int e = blockIdx.x * blockDim.x + threadIdx.x;
    if (e >= BE) return;
    int2 rc = g_rc[e];
    int pos = atomicAdd(&g_cursor[rc.x], 1);
    float nm = g_dinv[rc.x] * g_dinv[rc.y];
    g_csr[pos] = make_int2(rc.y, __float_as_int(nm));
}

// ---------------------------------------------------------------------------
// t = (relu?)(in) @ W^T + b  — packed f32x2, 4 rows per warp, 32 rows per block
template <bool RELU>
__global__ void __launch_bounds__(256)
linear_k(const float* __restrict__ in, const float* __restrict__ W,
         const float* __restrict__ bias, float* __restrict__ out) {
    __shared__ float2 sWp[64 * 32];   // [k][l] = (W[l][k], W[l+32][k])
    __shared__ float2 sx2[32 * 64];   // [r][k] = (v,v) replicated
    __shared__ float  sb[64];
    int tid = threadIdx.x;
    int row0 = blockIdx.x * 32;

    for (int idx = tid; idx < 2048; idx += 256) {
        int k = idx >> 5, l = idx & 31;
        sWp[idx] = make_float2(W[l * 64 + k], W[(l + 32) * 64 + k]);
    }
    if (tid < 64) sb[tid] = bias[tid];
    for (int idx = tid; idx < 2048; idx += 256) {
        int r = idx >> 6, k = idx & 63;
        float v = in[(size_t)(row0 + r) * 64 + k];
        if (RELU) v = fmaxf(v, 0.f);
        sx2[idx] = make_float2(v, v);
    }
    __syncthreads();

    int w = tid >> 5, l = tid & 31;
    int r0 = w * 4;
    unsigned long long bias2 = pack2(sb[l], sb[l + 32]);
    unsigned long long a0 = bias2, a1 = bias2, a2 = bias2, a3 = bias2;

    const unsigned long long* wp = (const unsigned long long*)sWp;
    const unsigned long long* xp = (const unsigned long long*)sx2;
#pragma unroll
    for (int k = 0; k < 64; k++) {
        unsigned long long wk = wp[k * 32 + l];
        fma2(a0, wk, xp[(r0 + 0) * 64 + k]);
        fma2(a1, wk, xp[(r0 + 1) * 64 + k]);
        fma2(a2, wk, xp[(r0 + 2) * 64 + k]);
        fma2(a3, wk, xp[(r0 + 3) * 64 + k]);
    }
    float lo, hi;
#define STORE_ROW(AJ, J)                                                      \
    unpack2(AJ, lo, hi);                                                      \
    out[(size_t)(row0 + r0 + J) * 64 + l]      = lo;                          \
    out[(size_t)(row0 + r0 + J) * 64 + l + 32] = hi;
    STORE_ROW(a0, 0) STORE_ROW(a1, 1) STORE_ROW(a2, 2) STORE_ROW(a3, 3)
#undef STORE_ROW
}

// ---------------------------------------------------------------------------
// CSR gather SpMM: one warp per node; lane owns features (2l,2l+1) as f32x2.
// NO register cap (previous rounds' __launch_bounds__(256,8) forced 32 regs
// -> spills / unroll collapse in the hot loop).
__global__ void __launch_bounds__(256)
spmm_k(const float* __restrict__ t, float* __restrict__ out) {
    int warp = (blockIdx.x * blockDim.x + threadIdx.x) >> 5;
    if (warp >= BN) return;
    int lane = threadIdx.x & 31;
    int start = g_rowstart[warp];
    int cnt   = g_degi[warp];

    const unsigned long long* t64 = (const unsigned long long*)t;
    unsigned long long acc = 0;
#pragma unroll 4
    for (int e = 0; e < cnt; e++) {
        int2 meta = __ldg(&g_csr[start + e]);        // warp-uniform broadcast
        unsigned long long nm2;
        asm("mov.b64 %0, {%1, %1};" : "=l"(nm2) : "r"(meta.y));
        unsigned long long v = __ldg(t64 + (size_t)meta.x * 32 + lane);
        fma2(acc, nm2, v);
    }
    float lo, hi;
    unpack2(acc, lo, hi);
    reinterpret_cast<float2*>(out + (size_t)warp * 64)[lane] = make_float2(lo, hi);
}

// ---------------------------------------------------------------------------
extern "C" void kernel_launch(void* const* d_in, const int* in_sizes, int n_in,
                              void* d_out, int out_size) {
    const float* x = nullptr;
    const void*  ei = nullptr;
    const float* Ws[3] = {nullptr, nullptr, nullptr};
    const float* bs[3] = {nullptr, nullptr, nullptr};
    int nW = 0, nb = 0;
    for (int i = 0; i < n_in; i++) {
        long long sz = in_sizes[i];
        if (sz == (long long)BN * FF)      x  = (const float*)d_in[i];
        else if (sz == (long long)BE * 2)  ei = d_in[i];
        else if (sz == FF * FF) { if (nW < 3) Ws[nW++] = (const float*)d_in[i]; }
        else if (sz == FF)      { if (nb < 3) bs[nb++] = (const float*)d_in[i]; }
    }
    float* out = (float*)d_out;

    int   *degi;
    float *t, *pA, *pB;
    cudaGetSymbolAddress((void**)&degi, g_degi);
    cudaGetSymbolAddress((void**)&t,    g_t);
    cudaGetSymbolAddress((void**)&pA,   g_pA);
    cudaGetSymbolAddress((void**)&pB,   g_pB);

    const int TPB = 256;
    const int edgeBlocks = (BE + TPB - 1) / TPB;     // 5000
    const int nodeBlocks = (BN + TPB - 1) / TPB;     // 313
    const int spmmBlocks = (BN * 32 + TPB - 1) / TPB;// 10000
    const int linBlocks  = BN / 32;                  // 2500

    // CSR build (4 launches; fill_k sits at capture slot 3)
    setup_k<<<nodeBlocks, TPB>>>(ei, degi);          // 0
    edges_k<<<edgeBlocks, TPB>>>(ei);                // 1
    scan_k <<<SCAN_BLKS, 1024>>>();                  // 2
    fill_k <<<edgeBlocks, TPB>>>();                  // 3  <- ncu capture

    // layers
    linear_k<false><<<linBlocks, TPB>>>(x, Ws[0], bs[0], t);   // 4
    spmm_k<<<spmmBlocks, TPB>>>(t, pA);                        // 5
    linear_k<true ><<<linBlocks, TPB>>>(pA, Ws[1], bs[1], t);  // 6
    spmm_k<<<spmmBlocks, TPB>>>(t, pB);                        // 7
    linear_k<true ><<<linBlocks, TPB>>>(pB, Ws[2], bs[2], t);  // 8
    spmm_k<<<spmmBlocks, TPB>>>(t, out);                       // 9
}

// round 9
// speedup vs baseline: 1.1357x; 1.0488x over previous
#include <cuda_runtime.h>
#include <cuda_bf16.h>
#include <cstdint>

#define BB 8
#define NN 10000
#define EE 160000
#define FF 64
#define BN (BB * NN)          // 80000 nodes
#define BE (BB * EE)          // 1280000 edges
#define SCAN_BLKS ((BN + 1023) / 1024)   // 79

#define FLAG_AGG    (1ULL << 62)
#define FLAG_PREFIX (2ULL << 62)
#define VAL_MASK    ((1ULL << 62) - 1)

typedef unsigned long long u64;

// ---- scratch (device globals; no allocation allowed) ----
__device__ int   g_is64;
__device__ int   g_degi[BN];
__device__ float g_dinv[BN];
__device__ int   g_rowstart[BN];
__device__ int   g_cursor[BN];
__device__ u64   g_state[SCAN_BLKS];
__device__ int2  g_csr[BE];       // {col, norm-bits} grouped by row
__device__ float g_t[BN * FF];
__device__ float g_pA[BN * FF];
__device__ float g_pB[BN * FF];

// ---------------------------------------------------------------------------
__device__ __forceinline__ void fma2(u64& acc, u64 a, u64 b) {
    asm("fma.rn.f32x2 %0, %1, %2, %0;" : "+l"(acc) : "l"(a), "l"(b));
}
__device__ __forceinline__ u64 pack2(float lo, float hi) {
    u64 r;
    asm("mov.b64 %0, {%1, %2};" : "=l"(r) : "f"(lo), "f"(hi));
    return r;
}
__device__ __forceinline__ u64 splat(float v) {
    u64 r;
    asm("mov.b64 %0, {%1, %1};" : "=l"(r) : "f"(v));
    return r;
}
__device__ __forceinline__ void unpack2(u64 v, float& lo, float& hi) {
    asm("mov.b64 {%0, %1}, %2;" : "=f"(lo), "=f"(hi) : "l"(v));
}

// decode edge e from edge_index (either width), clamped
__device__ __forceinline__ void decode_edge(const void* ei, int e, int is64,
                                            int& r, int& c) {
    if (is64) {
        const long long* p = (const long long*)ei;
        r = (int)p[2 * e];
        c = (int)p[2 * e + 1];
    } else {
        const int* p = (const int*)ei;
        r = p[2 * e];
        c = p[2 * e + 1];
    }
    r = min(max(r, 0), NN - 1);
    c = min(max(c, 0), NN - 1);
    int b = e / EE;
    r += b * NN;
    c += b * NN;
}

// ---------------------------------------------------------------------------
// zero degi + lookback state; block 0 warp 0 does parallel dtype detection
__global__ void setup_k(const void* ei, int* __restrict__ degp) {
    int i = blockIdx.x * blockDim.x + threadIdx.x;
    for (; i < BN; i += gridDim.x * blockDim.x) degp[i] = 0;
    if (blockIdx.x == 0 && threadIdx.x < 32) {
        if (threadIdx.x < SCAN_BLKS) {
            g_state[threadIdx.x] = 0;
            if (threadIdx.x + 32 < SCAN_BLKS) g_state[threadIdx.x + 32] = 0;
            if (threadIdx.x + 64 < SCAN_BLKS) g_state[threadIdx.x + 64] = 0;
        }
        const long long* p = (const long long*)ei;
        long long v0 = p[threadIdx.x];
        long long v1 = p[threadIdx.x + 32];
        bool bad = (v0 < 0) | (v0 >= NN) | (v1 < 0) | (v1 >= NN);
        unsigned m = __ballot_sync(0xffffffffu, bad);
        if (threadIdx.x == 0) g_is64 = (m == 0) ? 1 : 0;
    }
}

// degree histogram only (no rc staging)
__global__ void edges_k(const void* __restrict__ ei) {
    int e = blockIdx.x * blockDim.x + threadIdx.x;
    if (e >= BE) return;
    int r, c;
    decode_edge(ei, e, g_is64, r, c);
    atomicAdd(&g_degi[r], 1);
}

// ---------------------------------------------------------------------------
// single-kernel decoupled-lookback scan; fused dinv + cursor init
__global__ void __launch_bounds__(1024, 1) scan_k() {
    __shared__ int warpsum[32];
    __shared__ int sTot;
    __shared__ u64 sBase;
    int tid = threadIdx.x, lane = tid & 31, wid = tid >> 5;
    int b = blockIdx.x;
    int i = b * 1024 + tid;

    int v = (i < BN) ? g_degi[i] : 0;
    int x = v;
#pragma unroll
    for (int off = 1; off < 32; off <<= 1) {
        int y = __shfl_up_sync(0xffffffffu, x, off);
        if (lane >= off) x += y;
    }
    if (lane == 31) warpsum[wid] = x;
    __syncthreads();

    if (wid == 0) {
        int s = warpsum[lane];
        int xs = s;
#pragma unroll
        for (int off = 1; off < 32; off <<= 1) {
            int y = __shfl_up_sync(0xffffffffu, xs, off);
            if (lane >= off) xs += y;
        }
        warpsum[lane] = xs - s;
        if (lane == 31) sTot = xs;
        __syncwarp();
        int tot = sTot;

        if (b == 0) {
            if (lane == 0) {
                sBase = 0;
                atomicExch(&g_state[0], FLAG_PREFIX | (u64)tot);
            }
        } else {
            if (lane == 0)
                atomicExch(&g_state[b], FLAG_AGG | (u64)tot);
            u64 run = 0;
            int j = b - 1;
            while (true) {
                int idx = j - lane;
                u64 s64;
                if (idx >= 0) {
                    do {
                        s64 = *(volatile u64*)&g_state[idx];
                    } while ((s64 >> 62) == 0);
                } else {
                    s64 = FLAG_PREFIX;
                }
                unsigned f = (unsigned)(s64 >> 62);
                u64 val = s64 & VAL_MASK;
                unsigned pm = __ballot_sync(0xffffffffu, f == 2);
                if (pm) {
                    int lp = __ffs(pm) - 1;
                    u64 c2 = (lane <= lp) ? val : 0;
#pragma unroll
                    for (int o = 16; o; o >>= 1)
                        c2 += __shfl_down_sync(0xffffffffu, c2, o);
                    run += __shfl_sync(0xffffffffu, c2, 0);
                    break;
                } else {
                    u64 c2 = val;
#pragma unroll
                    for (int o = 16; o; o >>= 1)
                        c2 += __shfl_down_sync(0xffffffffu, c2, o);
                    run += __shfl_sync(0xffffffffu, c2, 0);
                    j -= 32;
                }
            }
            if (lane == 0) {
                sBase = run;
                atomicExch(&g_state[b], FLAG_PREFIX | (run + (u64)tot));
            }
        }
    }
    __syncthreads();

    if (i < BN) {
        int start = (int)sBase + warpsum[wid] + (x - v);
        g_rowstart[i] = start;
        g_cursor[i]   = start;
        g_dinv[i] = v > 0 ? rsqrtf((float)v) : 0.f;
    }
}

// scatter edges into CSR slots (re-decodes edge_index; no rc staging)
__global__ void fill_k(const void* __restrict__ ei) {
    int e = blockIdx.x * blockDim.x + threadIdx.x;
    if (e >= BE) return;
    int r, c;
    decode_edge(ei, e, g_is64, r, c);
    int pos = atomicAdd(&g_cursor[r], 1);
    float nm = g_dinv[r] * g_dinv[c];
    g_csr[pos] = make_int2(c, __float_as_int(nm));
}

// ---------------------------------------------------------------------------
// t = (relu?)(in) @ W^T + b — variant B: non-replicated x + register splat.
// Per k-pair: 2 lane-indexed weight LDS.64 (4 phases) + 4 broadcast x LDS.64
// (4 phases) for 8 FFMA2 -> 1.0 phase/FFMA2 (was 1.5).
template <bool RELU>
__global__ void __launch_bounds__(256)
linear_k(const float* __restrict__ in, const float* __restrict__ W,
         const float* __restrict__ bias, float* __restrict__ out) {
    __shared__ float2 sWp[64 * 32];   // [k][l] = (W[l][k], W[l+32][k]) 16KB
    __shared__ float2 sx[32 * 32];    // [r][kp] = (x[2kp], x[2kp+1])    8KB
    __shared__ float  sb[64];
    int tid = threadIdx.x;
    int row0 = blockIdx.x * 32;

    for (int idx = tid; idx < 2048; idx += 256) {
        int k = idx >> 5, l = idx & 31;
        sWp[idx] = make_float2(W[l * 64 + k], W[(l + 32) * 64 + k]);
    }
    if (tid < 64) sb[tid] = bias[tid];
    {
        const float2* in2 = (const float2*)(in + (size_t)row0 * 64);
        for (int idx = tid; idx < 1024; idx += 256) {
            float2 v = in2[idx];
            if (RELU) { v.x = fmaxf(v.x, 0.f); v.y = fmaxf(v.y, 0.f); }
            sx[idx] = v;
        }
    }
    __syncthreads();

    int w = tid >> 5, l = tid & 31;
    int r0 = w * 4;
    u64 bias2 = pack2(sb[l], sb[l + 32]);
    u64 a0 = bias2, a1 = bias2, a2 = bias2, a3 = bias2;

    const u64* wp = (const u64*)sWp;
#pragma unroll
    for (int kp = 0; kp < 32; kp++) {
        u64 w0 = wp[(2 * kp) * 32 + l];
        u64 w1 = wp[(2 * kp + 1) * 32 + l];
        float2 x0 = sx[(r0 + 0) * 32 + kp];
        float2 x1 = sx[(r0 + 1) * 32 + kp];
        float2 x2 = sx[(r0 + 2) * 32 + kp];
        float2 x3 = sx[(r0 + 3) * 32 + kp];
        fma2(a0, w0, splat(x0.x)); fma2(a0, w1, splat(x0.y));
        fma2(a1, w0, splat(x1.x)); fma2(a1, w1, splat(x1.y));
        fma2(a2, w0, splat(x2.x)); fma2(a2, w1, splat(x2.y));
        fma2(a3, w0, splat(x3.x)); fma2(a3, w1, splat(x3.y));
    }
    float lo, hi;
#define STORE_ROW(AJ, J)                                                      \
    unpack2(AJ, lo, hi);                                                      \
    out[(size_t)(row0 + r0 + J) * 64 + l]      = lo;                          \
    out[(size_t)(row0 + r0 + J) * 64 + l + 32] = hi;
    STORE_ROW(a0, 0) STORE_ROW(a1, 1) STORE_ROW(a2, 2) STORE_ROW(a3, 3)
#undef STORE_ROW
}

// ---------------------------------------------------------------------------
// CSR gather SpMM: one warp per node, lane owns f32x2 features; one-ahead
// meta prefetch breaks the meta->v dependency so v-loads batch at MLP~4.
__global__ void __launch_bounds__(256)
spmm_k(const float* __restrict__ t, float* __restrict__ out) {
    int warp = (blockIdx.x * blockDim.x + threadIdx.x) >> 5;
    if (warp >= BN) return;
    int lane = threadIdx.x & 31;
    int start = g_rowstart[warp];
    int cnt   = g_degi[warp];

    const u64* t64 = (const u64*)t;
    u64 acc = 0;
    if (cnt > 0) {
        int2 m = __ldg(&g_csr[start]);
#pragma unroll 4
        for (int e = 0; e < cnt; e++) {
            int2 mn = (e + 1 < cnt) ? __ldg(&g_csr[start + e + 1]) : m;
            u64 nm2 = splat(__int_as_float(m.y));
            u64 v = __ldg(t64 + (size_t)m.x * 32 + lane);
            fma2(acc, nm2, v);
            m = mn;
        }
    }
    float lo, hi;
    unpack2(acc, lo, hi);
    reinterpret_cast<float2*>(out + (size_t)warp * 64)[lane] = make_float2(lo, hi);
}

// ---------------------------------------------------------------------------
extern "C" void kernel_launch(void* const* d_in, const int* in_sizes, int n_in,
                              void* d_out, int out_size) {
    const float* x = nullptr;
    const void*  ei = nullptr;
    const float* Ws[3] = {nullptr, nullptr, nullptr};
    const float* bs[3] = {nullptr, nullptr, nullptr};
    int nW = 0, nb = 0;
    for (int i = 0; i < n_in; i++) {
        long long sz = in_sizes[i];
        if (sz == (long long)BN * FF)      x  = (const float*)d_in[i];
        else if (sz == (long long)BE * 2)  ei = d_in[i];
        else if (sz == FF * FF) { if (nW < 3) Ws[nW++] = (const float*)d_in[i]; }
        else if (sz == FF)      { if (nb < 3) bs[nb++] = (const float*)d_in[i]; }
    }
    float* out = (float*)d_out;

    int   *degi;
    float *t, *pA, *pB;
    cudaGetSymbolAddress((void**)&degi, g_degi);
    cudaGetSymbolAddress((void**)&t,    g_t);
    cudaGetSymbolAddress((void**)&pA,   g_pA);
    cudaGetSymbolAddress((void**)&pB,   g_pB);

    const int TPB = 256;
    const int edgeBlocks = (BE + TPB - 1) / TPB;     // 5000
    const int nodeBlocks = (BN + TPB - 1) / TPB;     // 313
    const int spmmBlocks = (BN * 32 + TPB - 1) / TPB;// 10000
    const int linBlocks  = BN / 32;                  // 2500

    setup_k<<<nodeBlocks, TPB>>>(ei, degi);                    // 0
    edges_k<<<edgeBlocks, TPB>>>(ei);                          // 1
    scan_k <<<SCAN_BLKS, 1024>>>();                            // 2
    linear_k<false><<<linBlocks, TPB>>>(x, Ws[0], bs[0], t);   // 3 <- ncu
    fill_k <<<edgeBlocks, TPB>>>(ei);                          // 4
    spmm_k<<<spmmBlocks, TPB>>>(t, pA);                        // 5
    linear_k<true ><<<linBlocks, TPB>>>(pA, Ws[1], bs[1], t);  // 6
    spmm_k<<<spmmBlocks, TPB>>>(t, pB);                        // 7
    linear_k<true ><<<linBlocks, TPB>>>(pB, Ws[2], bs[2], t);  // 8
    spmm_k<<<spmmBlocks, TPB>>>(t, out);                       // 9
}

// round 10
// speedup vs baseline: 1.3627x; 1.1999x over previous
#include <cuda_runtime.h>
#include <cuda_bf16.h>
#include <cstdint>

#define BB 8
#define NN 10000
#define EE 160000
#define FF 64
#define BN (BB * NN)          // 80000 nodes
#define BE (BB * EE)          // 1280000 edges
#define SCAN_BLKS ((BN + 1023) / 1024)   // 79

#define FLAG_AGG    (1ULL << 62)
#define FLAG_PREFIX (2ULL << 62)
#define VAL_MASK    ((1ULL << 62) - 1)

typedef unsigned long long u64;

// ---- scratch (device globals; no allocation allowed) ----
__device__ int   g_is64;
__device__ int   g_degi[BN];
__device__ float g_dinv[BN];
__device__ int   g_rowstart[BN];
__device__ int   g_cursor[BN];
__device__ u64   g_state[SCAN_BLKS];
__device__ int2  g_csr[BE];       // {col, norm-bits} grouped by row
__device__ float g_t[BN * FF];
__device__ float g_pA[BN * FF];
__device__ float g_pB[BN * FF];

// ---------------------------------------------------------------------------
__device__ __forceinline__ void fma2(u64& acc, u64 a, u64 b) {
    asm("fma.rn.f32x2 %0, %1, %2, %0;" : "+l"(acc) : "l"(a), "l"(b));
}
__device__ __forceinline__ u64 pack2(float lo, float hi) {
    u64 r;
    asm("mov.b64 %0, {%1, %2};" : "=l"(r) : "f"(lo), "f"(hi));
    return r;
}
__device__ __forceinline__ u64 splat(float v) {
    u64 r;
    asm("mov.b64 %0, {%1, %1};" : "=l"(r) : "f"(v));
    return r;
}
__device__ __forceinline__ void unpack2(u64 v, float& lo, float& hi) {
    asm("mov.b64 {%0, %1}, %2;" : "=f"(lo), "=f"(hi) : "l"(v));
}

// decode edge e from edge_index (either width), clamped
__device__ __forceinline__ void decode_edge(const void* ei, int e, int is64,
                                            int& r, int& c) {
    if (is64) {
        const long long* p = (const long long*)ei;
        r = (int)p[2 * e];
        c = (int)p[2 * e + 1];
    } else {
        const int* p = (const int*)ei;
        r = p[2 * e];
        c = p[2 * e + 1];
    }
    r = min(max(r, 0), NN - 1);
    c = min(max(c, 0), NN - 1);
    int b = e / EE;
    r += b * NN;
    c += b * NN;
}

// ---------------------------------------------------------------------------
// zero degi + lookback state; block 0 warp 0 does parallel dtype detection
__global__ void setup_k(const void* ei, int* __restrict__ degp) {
    int i = blockIdx.x * blockDim.x + threadIdx.x;
    for (; i < BN; i += gridDim.x * blockDim.x) degp[i] = 0;
    if (blockIdx.x == 0 && threadIdx.x < 32) {
        if (threadIdx.x < SCAN_BLKS) {
            g_state[threadIdx.x] = 0;
            if (threadIdx.x + 32 < SCAN_BLKS) g_state[threadIdx.x + 32] = 0;
            if (threadIdx.x + 64 < SCAN_BLKS) g_state[threadIdx.x + 64] = 0;
        }
        const long long* p = (const long long*)ei;
        long long v0 = p[threadIdx.x];
        long long v1 = p[threadIdx.x + 32];
        bool bad = (v0 < 0) | (v0 >= NN) | (v1 < 0) | (v1 >= NN);
        unsigned m = __ballot_sync(0xffffffffu, bad);
        if (threadIdx.x == 0) g_is64 = (m == 0) ? 1 : 0;
    }
}

// degree histogram
__global__ void edges_k(const void* __restrict__ ei) {
    int e = blockIdx.x * blockDim.x + threadIdx.x;
    if (e >= BE) return;
    int r, c;
    decode_edge(ei, e, g_is64, r, c);
    atomicAdd(&g_degi[r], 1);
}

// ---------------------------------------------------------------------------
// single-kernel decoupled-lookback scan; fused dinv + cursor init
__global__ void __launch_bounds__(1024, 1) scan_k() {
    __shared__ int warpsum[32];
    __shared__ int sTot;
    __shared__ u64 sBase;
    int tid = threadIdx.x, lane = tid & 31, wid = tid >> 5;
    int b = blockIdx.x;
    int i = b * 1024 + tid;

    int v = (i < BN) ? g_degi[i] : 0;
    int x = v;
#pragma unroll
    for (int off = 1; off < 32; off <<= 1) {
        int y = __shfl_up_sync(0xffffffffu, x, off);
        if (lane >= off) x += y;
    }
    if (lane == 31) warpsum[wid] = x;
    __syncthreads();

    if (wid == 0) {
        int s = warpsum[lane];
        int xs = s;
#pragma unroll
        for (int off = 1; off < 32; off <<= 1) {
            int y = __shfl_up_sync(0xffffffffu, xs, off);
            if (lane >= off) xs += y;
        }
        warpsum[lane] = xs - s;
        if (lane == 31) sTot = xs;
        __syncwarp();
        int tot = sTot;

        if (b == 0) {
            if (lane == 0) {
                sBase = 0;
                atomicExch(&g_state[0], FLAG_PREFIX | (u64)tot);
            }
        } else {
            if (lane == 0)
                atomicExch(&g_state[b], FLAG_AGG | (u64)tot);
            u64 run = 0;
            int j = b - 1;
            while (true) {
                int idx = j - lane;
                u64 s64;
                if (idx >= 0) {
                    do {
                        s64 = *(volatile u64*)&g_state[idx];
                    } while ((s64 >> 62) == 0);
                } else {
                    s64 = FLAG_PREFIX;
                }
                unsigned f = (unsigned)(s64 >> 62);
                u64 val = s64 & VAL_MASK;
                unsigned pm = __ballot_sync(0xffffffffu, f == 2);
                if (pm) {
                    int lp = __ffs(pm) - 1;
                    u64 c2 = (lane <= lp) ? val : 0;
#pragma unroll
                    for (int o = 16; o; o >>= 1)
                        c2 += __shfl_down_sync(0xffffffffu, c2, o);
                    run += __shfl_sync(0xffffffffu, c2, 0);
                    break;
                } else {
                    u64 c2 = val;
#pragma unroll
                    for (int o = 16; o; o >>= 1)
                        c2 += __shfl_down_sync(0xffffffffu, c2, o);
                    run += __shfl_sync(0xffffffffu, c2, 0);
                    j -= 32;
                }
            }
            if (lane == 0) {
                sBase = run;
                atomicExch(&g_state[b], FLAG_PREFIX | (run + (u64)tot));
            }
        }
    }
    __syncthreads();

    if (i < BN) {
        int start = (int)sBase + warpsum[wid] + (x - v);
        g_rowstart[i] = start;
        g_cursor[i]   = start;
        g_dinv[i] = v > 0 ? rsqrtf((float)v) : 0.f;
    }
}

// scatter edges into CSR slots
__global__ void fill_k(const void* __restrict__ ei) {
    int e = blockIdx.x * blockDim.x + threadIdx.x;
    if (e >= BE) return;
    int r, c;
    decode_edge(ei, e, g_is64, r, c);
    int pos = atomicAdd(&g_cursor[r], 1);
    float nm = g_dinv[r] * g_dinv[c];
    g_csr[pos] = make_int2(c, __float_as_int(nm));
}

// ---------------------------------------------------------------------------
// t = (relu?)(in) @ W^T + b — row-paired f32x2 accumulators.
// acc = (out[r0][o], out[r1][o]): x operand pre-paired (x[r0][k],x[r1][k])
// broadcast from smem (LDS.128 = 2 k's, 1 wavefront); W splats hoisted
// across 4 row-pairs. Per inner iter: 32 FFMA2, 16 wavefronts, ~54 issues.
// 64 rows/block, 8 rows (4 pairs) per thread.
template <bool RELU>
__global__ void __launch_bounds__(256)
linear_k(const float* __restrict__ in, const float* __restrict__ W,
         const float* __restrict__ bias, float* __restrict__ out) {
    __shared__ float4 sW4[32 * 32];  // [kp][l]=(W[l][2kp],W[l+32][2kp],W[l][2kp+1],W[l+32][2kp+1])
    __shared__ u64    sxp[32 * 64];  // [rpg][k] = (x[2rpg][k], x[2rpg+1][k])
    __shared__ float  sb[64];
    int tid = threadIdx.x;
    int row0 = blockIdx.x * 64;

    for (int idx = tid; idx < 1024; idx += 256) {
        int kp = idx >> 5, l = idx & 31;
        sW4[idx] = make_float4(W[l * 64 + 2 * kp], W[(l + 32) * 64 + 2 * kp],
                               W[l * 64 + 2 * kp + 1], W[(l + 32) * 64 + 2 * kp + 1]);
    }
    if (tid < 64) sb[tid] = bias[tid];
    for (int idx = tid; idx < 2048; idx += 256) {
        int rpg = idx >> 6, k = idx & 63;
        float v0 = in[(size_t)(row0 + 2 * rpg) * 64 + k];
        float v1 = in[(size_t)(row0 + 2 * rpg + 1) * 64 + k];
        if (RELU) { v0 = fmaxf(v0, 0.f); v1 = fmaxf(v1, 0.f); }
        sxp[idx] = pack2(v0, v1);
    }
    __syncthreads();

    int w = tid >> 5, l = tid & 31;
    u64 accL[4], accH[4];
    {
        u64 bL = splat(sb[l]), bH = splat(sb[l + 32]);
#pragma unroll
        for (int rp = 0; rp < 4; rp++) { accL[rp] = bL; accH[rp] = bH; }
    }

    const u64* xbase = sxp + (size_t)(w * 4) * 64;
#pragma unroll
    for (int kq = 0; kq < 16; kq++) {
        float4 wq0 = sW4[(2 * kq) * 32 + l];       // k=4kq, 4kq+1
        float4 wq1 = sW4[(2 * kq + 1) * 32 + l];   // k=4kq+2, 4kq+3
        u64 wl0 = splat(wq0.x), wh0 = splat(wq0.y);
        u64 wl1 = splat(wq0.z), wh1 = splat(wq0.w);
        u64 wl2 = splat(wq1.x), wh2 = splat(wq1.y);
        u64 wl3 = splat(wq1.z), wh3 = splat(wq1.w);
#pragma unroll
        for (int rp = 0; rp < 4; rp++) {
            const u64* xr = xbase + rp * 64 + 4 * kq;
            u64 x0 = xr[0], x1 = xr[1], x2 = xr[2], x3 = xr[3];
            fma2(accL[rp], x0, wl0); fma2(accH[rp], x0, wh0);
            fma2(accL[rp], x1, wl1); fma2(accH[rp], x1, wh1);
            fma2(accL[rp], x2, wl2); fma2(accH[rp], x2, wh2);
            fma2(accL[rp], x3, wl3); fma2(accH[rp], x3, wh3);
        }
    }
    int rbase = row0 + w * 8;
#pragma unroll
    for (int rp = 0; rp < 4; rp++) {
        float a, b;
        unpack2(accL[rp], a, b);
        out[(size_t)(rbase + 2 * rp) * 64 + l]          = a;
        out[(size_t)(rbase + 2 * rp + 1) * 64 + l]      = b;
        unpack2(accH[rp], a, b);
        out[(size_t)(rbase + 2 * rp) * 64 + l + 32]     = a;
        out[(size_t)(rbase + 2 * rp + 1) * 64 + l + 32] = b;
    }
}

// ---------------------------------------------------------------------------
// CSR gather SpMM: one warp per node, lane owns f32x2 features; one-ahead
// meta prefetch. Measured at LTS-cap floor (~26us/layer).
__global__ void __launch_bounds__(256)
spmm_k(const float* __restrict__ t, float* __restrict__ out) {
    int warp = (blockIdx.x * blockDim.x + threadIdx.x) >> 5;
    if (warp >= BN) return;
    int lane = threadIdx.x & 31;
    int start = g_rowstart[warp];
    int cnt   = g_degi[warp];

    const u64* t64 = (const u64*)t;
    u64 acc = 0;
    if (cnt > 0) {
        int2 m = __ldg(&g_csr[start]);
#pragma unroll 4
        for (int e = 0; e < cnt; e++) {
            int2 mn = (e + 1 < cnt) ? __ldg(&g_csr[start + e + 1]) : m;
            u64 nm2 = splat(__int_as_float(m.y));
            u64 v = __ldg(t64 + (size_t)m.x * 32 + lane);
            fma2(acc, nm2, v);
            m = mn;
        }
    }
    float lo, hi;
    unpack2(acc, lo, hi);
    reinterpret_cast<float2*>(out + (size_t)warp * 64)[lane] = make_float2(lo, hi);
}

// ---------------------------------------------------------------------------
extern "C" void kernel_launch(void* const* d_in, const int* in_sizes, int n_in,
                              void* d_out, int out_size) {
    const float* x = nullptr;
    const void*  ei = nullptr;
    const float* Ws[3] = {nullptr, nullptr, nullptr};
    const float* bs[3] = {nullptr, nullptr, nullptr};
    int nW = 0, nb = 0;
    for (int i = 0; i < n_in; i++) {
        long long sz = in_sizes[i];
        if (sz == (long long)BN * FF)      x  = (const float*)d_in[i];
        else if (sz == (long long)BE * 2)  ei = d_in[i];
        else if (sz == FF * FF) { if (nW < 3) Ws[nW++] = (const float*)d_in[i]; }
        else if (sz == FF)      { if (nb < 3) bs[nb++] = (const float*)d_in[i]; }
    }
    float* out = (float*)d_out;

    int   *degi;
    float *t, *pA, *pB;
    cudaGetSymbolAddress((void**)&degi, g_degi);
    cudaGetSymbolAddress((void**)&t,    g_t);
    cudaGetSymbolAddress((void**)&pA,   g_pA);
    cudaGetSymbolAddress((void**)&pB,   g_pB);

    const int TPB = 256;
    const int edgeBlocks = (BE + TPB - 1) / TPB;     // 5000
    const int nodeBlocks = (BN + TPB - 1) / TPB;     // 313
    const int spmmBlocks = (BN * 32 + TPB - 1) / TPB;// 10000
    const int linBlocks  = BN / 64;                  // 1250

    setup_k<<<nodeBlocks, TPB>>>(ei, degi);                    // 0
    edges_k<<<edgeBlocks, TPB>>>(ei);                          // 1
    scan_k <<<SCAN_BLKS, 1024>>>();                            // 2
    linear_k<false><<<linBlocks, TPB>>>(x, Ws[0], bs[0], t);   // 3 <- ncu
    fill_k <<<edgeBlocks, TPB>>>(ei);                          // 4
    spmm_k<<<spmmBlocks, TPB>>>(t, pA);                        // 5
    linear_k<true ><<<linBlocks, TPB>>>(pA, Ws[1], bs[1], t);  // 6
    spmm_k<<<spmmBlocks, TPB>>>(t, pB);                        // 7
    linear_k<true ><<<linBlocks, TPB>>>(pB, Ws[2], bs[2], t);  // 8
    spmm_k<<<spmmBlocks, TPB>>>(t, out);                       // 9
}

// round 11
// speedup vs baseline: 1.6717x; 1.2268x over previous
#include <cuda_runtime.h>
#include <cuda_bf16.h>
#include <cstdint>

#define BB 8
#define NN 10000
#define EE 160000
#define FF 64
#define BN (BB * NN)          // 80000 nodes
#define BE (BB * EE)          // 1280000 edges
#define SCAN_BLKS ((BN + 1023) / 1024)   // 79

#define FLAG_AGG    (1ULL << 62)
#define FLAG_PREFIX (2ULL << 62)
#define VAL_MASK    ((1ULL << 62) - 1)

typedef unsigned long long u64;
typedef unsigned int u32;

// ---- scratch (device globals; no allocation allowed) ----
__device__ int   g_is64;
__device__ int   g_degi[BN];
__device__ float g_dinv[BN];
__device__ int   g_rowstart[BN];
__device__ int   g_cursor[BN];
__device__ u64   g_state[SCAN_BLKS];
__device__ int2  g_csr[BE];            // {col, norm-bits} grouped by row
__device__ unsigned short g_tb[BN * FF];  // bf16 post-linear features (10MB)
__device__ float g_pA[BN * FF];
__device__ float g_pB[BN * FF];

// ---------------------------------------------------------------------------
__device__ __forceinline__ void fma2(u64& acc, u64 a, u64 b) {
    asm("fma.rn.f32x2 %0, %1, %2, %0;" : "+l"(acc) : "l"(a), "l"(b));
}
__device__ __forceinline__ u64 pack2(float lo, float hi) {
    u64 r;
    asm("mov.b64 %0, {%1, %2};" : "=l"(r) : "f"(lo), "f"(hi));
    return r;
}
__device__ __forceinline__ u64 splat(float v) {
    u64 r;
    asm("mov.b64 %0, {%1, %1};" : "=l"(r) : "f"(v));
    return r;
}
__device__ __forceinline__ void unpack2(u64 v, float& lo, float& hi) {
    asm("mov.b64 {%0, %1}, %2;" : "=f"(lo), "=f"(hi) : "l"(v));
}

__device__ __forceinline__ void decode_edge(const void* ei, int e, int is64,
                                            int& r, int& c) {
    if (is64) {
        const long long* p = (const long long*)ei;
        r = (int)p[2 * e];
        c = (int)p[2 * e + 1];
    } else {
        const int* p = (const int*)ei;
        r = p[2 * e];
        c = p[2 * e + 1];
    }
    r = min(max(r, 0), NN - 1);
    c = min(max(c, 0), NN - 1);
    int b = e / EE;
    r += b * NN;
    c += b * NN;
}

// ---------------------------------------------------------------------------
__global__ void setup_k(const void* ei, int* __restrict__ degp) {
    int i = blockIdx.x * blockDim.x + threadIdx.x;
    for (; i < BN; i += gridDim.x * blockDim.x) degp[i] = 0;
    if (blockIdx.x == 0 && threadIdx.x < 32) {
        if (threadIdx.x < SCAN_BLKS) {
            g_state[threadIdx.x] = 0;
            if (threadIdx.x + 32 < SCAN_BLKS) g_state[threadIdx.x + 32] = 0;
            if (threadIdx.x + 64 < SCAN_BLKS) g_state[threadIdx.x + 64] = 0;
        }
        const long long* p = (const long long*)ei;
        long long v0 = p[threadIdx.x];
        long long v1 = p[threadIdx.x + 32];
        bool bad = (v0 < 0) | (v0 >= NN) | (v1 < 0) | (v1 >= NN);
        unsigned m = __ballot_sync(0xffffffffu, bad);
        if (threadIdx.x == 0) g_is64 = (m == 0) ? 1 : 0;
    }
}

__global__ void edges_k(const void* __restrict__ ei) {
    int e = blockIdx.x * blockDim.x + threadIdx.x;
    if (e >= BE) return;
    int r, c;
    decode_edge(ei, e, g_is64, r, c);
    atomicAdd(&g_degi[r], 1);
}

// single-kernel decoupled-lookback scan; fused dinv + cursor init
__global__ void __launch_bounds__(1024, 1) scan_k() {
    __shared__ int warpsum[32];
    __shared__ int sTot;
    __shared__ u64 sBase;
    int tid = threadIdx.x, lane = tid & 31, wid = tid >> 5;
    int b = blockIdx.x;
    int i = b * 1024 + tid;

    int v = (i < BN) ? g_degi[i] : 0;
    int x = v;
#pragma unroll
    for (int off = 1; off < 32; off <<= 1) {
        int y = __shfl_up_sync(0xffffffffu, x, off);
        if (lane >= off) x += y;
    }
    if (lane == 31) warpsum[wid] = x;
    __syncthreads();

    if (wid == 0) {
        int s = warpsum[lane];
        int xs = s;
#pragma unroll
        for (int off = 1; off < 32; off <<= 1) {
            int y = __shfl_up_sync(0xffffffffu, xs, off);
            if (lane >= off) xs += y;
        }
        warpsum[lane] = xs - s;
        if (lane == 31) sTot = xs;
        __syncwarp();
        int tot = sTot;

        if (b == 0) {
            if (lane == 0) {
                sBase = 0;
                atomicExch(&g_state[0], FLAG_PREFIX | (u64)tot);
            }
        } else {
            if (lane == 0)
                atomicExch(&g_state[b], FLAG_AGG | (u64)tot);
            u64 run = 0;
            int j = b - 1;
            while (true) {
                int idx = j - lane;
                u64 s64;
                if (idx >= 0) {
                    do {
                        s64 = *(volatile u64*)&g_state[idx];
                    } while ((s64 >> 62) == 0);
                } else {
                    s64 = FLAG_PREFIX;
                }
                unsigned f = (unsigned)(s64 >> 62);
                u64 val = s64 & VAL_MASK;
                unsigned pm = __ballot_sync(0xffffffffu, f == 2);
                if (pm) {
                    int lp = __ffs(pm) - 1;
                    u64 c2 = (lane <= lp) ? val : 0;
#pragma unroll
                    for (int o = 16; o; o >>= 1)
                        c2 += __shfl_down_sync(0xffffffffu, c2, o);
                    run += __shfl_sync(0xffffffffu, c2, 0);
                    break;
                } else {
                    u64 c2 = val;
#pragma unroll
                    for (int o = 16; o; o >>= 1)
                        c2 += __shfl_down_sync(0xffffffffu, c2, o);
                    run += __shfl_sync(0xffffffffu, c2, 0);
                    j -= 32;
                }
            }
            if (lane == 0) {
                sBase = run;
                atomicExch(&g_state[b], FLAG_PREFIX | (run + (u64)tot));
            }
        }
    }
    __syncthreads();

    if (i < BN) {
        int start = (int)sBase + warpsum[wid] + (x - v);
        g_rowstart[i] = start;
        g_cursor[i]   = start;
        g_dinv[i] = v > 0 ? rsqrtf((float)v) : 0.f;
    }
}

__global__ void fill_k(const void* __restrict__ ei) {
    int e = blockIdx.x * blockDim.x + threadIdx.x;
    if (e >= BE) return;
    int r, c;
    decode_edge(ei, e, g_is64, r, c);
    int pos = atomicAdd(&g_cursor[r], 1);
    float nm = g_dinv[r] * g_dinv[c];
    g_csr[pos] = make_int2(c, __float_as_int(nm));
}

// ---------------------------------------------------------------------------
// t = (relu?)(in) @ W^T + b  ->  bf16 output.
// Row-paired f32x2 accumulators; W staged COALESCED (float2 linear reads,
// 4-way-conflict transpose STS into padded [32][33] float4 layout); x read
// via LDS.128 (ulonglong2). 64 rows/block, 8 rows/thread.
template <bool RELU>
__global__ void __launch_bounds__(256)
linear_k(const float* __restrict__ in, const float* __restrict__ W,
         const float* __restrict__ bias, unsigned short* __restrict__ out) {
    __shared__ float4 sW4[32 * 33];  // [kp][l] padded; c0=W[l][2kp] c1=W[l+32][2kp] c2=W[l][2kp+1] c3=W[l+32][2kp+1]
    __shared__ u64    sxp[32 * 64];  // [rpg][k] = (x[2rpg][k], x[2rpg+1][k])
    __shared__ float  sb[64];
    int tid = threadIdx.x;
    int row0 = blockIdx.x * 64;

    // W staging: coalesced float2 loads, scatter STS (4-way via pad)
    {
        const float2* W2 = (const float2*)W;
        for (int idx = tid; idx < 2048; idx += 256) {
            int o  = idx >> 5;          // 0..63
            int kp = idx & 31;          // k-pair
            float2 wv = W2[o * 32 + kp];          // W[o][2kp], W[o][2kp+1]
            float* base = (float*)&sW4[kp * 33 + (o & 31)];
            if (o < 32) { base[0] = wv.x; base[2] = wv.y; }
            else        { base[1] = wv.x; base[3] = wv.y; }
        }
    }
    if (tid < 64) sb[tid] = bias[tid];
    for (int idx = tid; idx < 2048; idx += 256) {
        int rpg = idx >> 6, k = idx & 63;
        float v0 = in[(size_t)(row0 + 2 * rpg) * 64 + k];
        float v1 = in[(size_t)(row0 + 2 * rpg + 1) * 64 + k];
        if (RELU) { v0 = fmaxf(v0, 0.f); v1 = fmaxf(v1, 0.f); }
        sxp[idx] = pack2(v0, v1);
    }
    __syncthreads();

    int w = tid >> 5, l = tid & 31;
    u64 accL[4], accH[4];
    {
        u64 bL = splat(sb[l]), bH = splat(sb[l + 32]);
#pragma unroll
        for (int rp = 0; rp < 4; rp++) { accL[rp] = bL; accH[rp] = bH; }
    }

    const u64* xbase = sxp + (size_t)(w * 4) * 64;
#pragma unroll
    for (int kq = 0; kq < 16; kq++) {
        float4 wq0 = sW4[(2 * kq) * 33 + l];       // k=4kq, 4kq+1
        float4 wq1 = sW4[(2 * kq + 1) * 33 + l];   // k=4kq+2, 4kq+3
        u64 wl0 = splat(wq0.x), wh0 = splat(wq0.y);
        u64 wl1 = splat(wq0.z), wh1 = splat(wq0.w);
        u64 wl2 = splat(wq1.x), wh2 = splat(wq1.y);
        u64 wl3 = splat(wq1.z), wh3 = splat(wq1.w);
#pragma unroll
        for (int rp = 0; rp < 4; rp++) {
            const ulonglong2* xr = (const ulonglong2*)(xbase + rp * 64 + 4 * kq);
            ulonglong2 p0 = xr[0];
            ulonglong2 p1 = xr[1];
            fma2(accL[rp], p0.x, wl0); fma2(accH[rp], p0.x, wh0);
            fma2(accL[rp], p0.y, wl1); fma2(accH[rp], p0.y, wh1);
            fma2(accL[rp], p1.x, wl2); fma2(accH[rp], p1.x, wh2);
            fma2(accL[rp], p1.y, wl3); fma2(accH[rp], p1.y, wh3);
        }
    }
    int rbase = row0 + w * 8;
#pragma unroll
    for (int rp = 0; rp < 4; rp++) {
        float a, b;
        unpack2(accL[rp], a, b);
        out[(size_t)(rbase + 2 * rp) * 64 + l] =
            __bfloat16_as_ushort(__float2bfloat16(a));
        out[(size_t)(rbase + 2 * rp + 1) * 64 + l] =
            __bfloat16_as_ushort(__float2bfloat16(b));
        unpack2(accH[rp], a, b);
        out[(size_t)(rbase + 2 * rp) * 64 + l + 32] =
            __bfloat16_as_ushort(__float2bfloat16(a));
        out[(size_t)(rbase + 2 * rp + 1) * 64 + l + 32] =
            __bfloat16_as_ushort(__float2bfloat16(b));
    }
}

// ---------------------------------------------------------------------------
// CSR gather SpMM over bf16 t: 128B/edge row (half traffic). Lane owns
// features (2l, 2l+1) packed in one u32; fp32 accumulate.
__global__ void __launch_bounds__(256)
spmm_k(const unsigned short* __restrict__ tb, float* __restrict__ out) {
    int warp = (blockIdx.x * blockDim.x + threadIdx.x) >> 5;
    if (warp >= BN) return;
    int lane = threadIdx.x & 31;
    int start = g_rowstart[warp];
    int cnt   = g_degi[warp];

    const u32* t32 = (const u32*)tb;
    float acc0 = 0.f, acc1 = 0.f;
    if (cnt > 0) {
        int2 m = __ldg(&g_csr[start]);
#pragma unroll 4
        for (int e = 0; e < cnt; e++) {
            int2 mn = (e + 1 < cnt) ? __ldg(&g_csr[start + e + 1]) : m;
            float nm = __int_as_float(m.y);
            u32 v = __ldg(t32 + (size_t)m.x * 32 + lane);
            acc0 = fmaf(nm, __uint_as_float(v << 16), acc0);
            acc1 = fmaf(nm, __uint_as_float(v & 0xffff0000u), acc1);
            m = mn;
        }
    }
    reinterpret_cast<float2*>(out + (size_t)warp * 64)[lane] =
        make_float2(acc0, acc1);
}

// ---------------------------------------------------------------------------
extern "C" void kernel_launch(void* const* d_in, const int* in_sizes, int n_in,
                              void* d_out, int out_size) {
    const float* x = nullptr;
    const void*  ei = nullptr;
    const float* Ws[3] = {nullptr, nullptr, nullptr};
    const float* bs[3] = {nullptr, nullptr, nullptr};
    int nW = 0, nb = 0;
    for (int i = 0; i < n_in; i++) {
        long long sz = in_sizes[i];
        if (sz == (long long)BN * FF)      x  = (const float*)d_in[i];
        else if (sz == (long long)BE * 2)  ei = d_in[i];
        else if (sz == FF * FF) { if (nW < 3) Ws[nW++] = (const float*)d_in[i]; }
        else if (sz == FF)      { if (nb < 3) bs[nb++] = (const float*)d_in[i]; }
    }
    float* out = (float*)d_out;

    int   *degi;
    unsigned short *tb;
    float *pA, *pB;
    cudaGetSymbolAddress((void**)&degi, g_degi);
    cudaGetSymbolAddress((void**)&tb,   g_tb);
    cudaGetSymbolAddress((void**)&pA,   g_pA);
    cudaGetSymbolAddress((void**)&pB,   g_pB);

    const int TPB = 256;
    const int edgeBlocks = (BE + TPB - 1) / TPB;     // 5000
    const int nodeBlocks = (BN + TPB - 1) / TPB;     // 313
    const int spmmBlocks = (BN * 32 + TPB - 1) / TPB;// 10000
    const int linBlocks  = BN / 64;                  // 1250

    setup_k<<<nodeBlocks, TPB>>>(ei, degi);                     // 0
    edges_k<<<edgeBlocks, TPB>>>(ei);                           // 1
    scan_k <<<SCAN_BLKS, 1024>>>();                             // 2
    linear_k<false><<<linBlocks, TPB>>>(x, Ws[0], bs[0], tb);   // 3 <- ncu
    fill_k <<<edgeBlocks, TPB>>>(ei);                           // 4
    spmm_k<<<spmmBlocks, TPB>>>(tb, pA);                        // 5
    linear_k<true ><<<linBlocks, TPB>>>(pA, Ws[1], bs[1], tb);  // 6
    spmm_k<<<spmmBlocks, TPB>>>(tb, pB);                        // 7
    linear_k<true ><<<linBlocks, TPB>>>(pB, Ws[2], bs[2], tb);  // 8
    spmm_k<<<spmmBlocks, TPB>>>(tb, out);                       // 9
}